// round 3
// baseline (speedup 1.0000x reference)
#include <cuda_runtime.h>

#define KCL   64
#define PD    32
#define NBLK  296
#define TILE  256
#define DETC  1e-16f

// ---- shared memory layout (bytes) ----
#define OFF_MUK2   0          // ull[32*32]    (packed cluster pairs, [p][k2])  8192 B
#define OFF_ASM    8192       // ull[256*17]   (mu_phi tile, p-pairs, pad)     34816 B
#define OFF_GT     43008      // float[64*257] (gamma tile transposed [k][pt]) 65792 B
#define OFF_EC     108800     // float[256]    exp(lcp) per point
#define OFF_NA     109824     // float[256]    ||x||^2 per point
#define OFF_AK     110848     // float[64]     pi_k * exp(-16*lck)
#define OFF_ICOV   111104     // float[64]     exp(-lck)
#define OFF_NB     111360     // float[64]     ||mu_k||^2
#define SMEM_BYTES 111616

// per-block partial sums: entries 0..2047 = M[k][p], 2048..2111 = N_k,
// 2112..2175 = E_k, 2176..2239 = S2_k ; layout [entry][block]
__device__ float g_scratch[2240 * NBLK];

__device__ __forceinline__ unsigned long long pk2(float lo, float hi) {
    unsigned long long u;
    asm("mov.b64 %0, {%1,%2};" : "=l"(u) : "f"(lo), "f"(hi));
    return u;
}
__device__ __forceinline__ void upk2(unsigned long long u, float& lo, float& hi) {
    asm("mov.b64 {%0,%1}, %2;" : "=f"(lo), "=f"(hi) : "l"(u));
}
__device__ __forceinline__ unsigned long long fma2(unsigned long long a,
                                                   unsigned long long b,
                                                   unsigned long long c) {
    unsigned long long d;
    asm("fma.rn.f32x2 %0, %1, %2, %3;" : "=l"(d) : "l"(a), "l"(b), "l"(c));
    return d;
}

__global__ __launch_bounds__(256, 1)
void deeplpm_main(const float* __restrict__ mu_phi,
                  const float* __restrict__ lcp_g,
                  const float* __restrict__ pi_k,
                  const float* __restrict__ mu_k,
                  const float* __restrict__ lck_g,
                  float* __restrict__ gamma_out,
                  int N) {
    extern __shared__ unsigned char sm[];
    unsigned long long* MUK2 = (unsigned long long*)(sm + OFF_MUK2);
    unsigned long long* ASMp = (unsigned long long*)(sm + OFF_ASM);
    float* GT   = (float*)(sm + OFF_GT);
    float* ECp  = (float*)(sm + OFF_EC);
    float* NAp  = (float*)(sm + OFF_NA);
    float* AK   = (float*)(sm + OFF_AK);
    float* ICOV = (float*)(sm + OFF_ICOV);
    float* NB   = (float*)(sm + OFF_NB);

    const int tid = threadIdx.x;

    // ---- init: pack mu_k pairs + per-cluster params ----
    for (int idx = tid; idx < 1024; idx += 256) {
        int k2 = idx & 31, p = idx >> 5;
        float b0 = mu_k[(2 * k2) * PD + p];
        float b1 = mu_k[(2 * k2 + 1) * PD + p];
        MUK2[p * 32 + k2] = pk2(b0, b1);
    }
    if (tid < KCL) {
        float lck = lck_g[tid];
        ICOV[tid] = __expf(-lck);
        AK[tid]   = pi_k[tid] * __expf(-16.0f * lck);
        float nb = 0.0f;
        #pragma unroll
        for (int p = 0; p < PD; ++p) {
            float v = mu_k[tid * PD + p];
            nb = fmaf(v, v, nb);
        }
        NB[tid] = nb;
    }
    __syncthreads();

    // GEMM2 role of this thread
    const int q  = tid >> 6;       // point-quarter 0..3
    const int r  = tid & 63;
    const int kp = r >> 1;         // cluster pair 0..31
    const int ph = r & 1;          // p-half 0/1
    const int gr0 = (2 * kp) * 257;
    const int gr1 = (2 * kp + 1) * 257;

    unsigned long long macc0[8], macc1[8];
    #pragma unroll
    for (int j = 0; j < 8; ++j) { macc0[j] = 0ull; macc1[j] = 0ull; }
    float nacc = 0.0f, eacc = 0.0f, sacc = 0.0f;

    const int tiles = (N + TILE - 1) >> 8;

    for (int tile = blockIdx.x; tile < tiles; tile += gridDim.x) {
        __syncthreads();   // protect shared from previous iteration's GEMM2 readers
        const int i = tile * TILE + tid;
        if (i < N) {
            // load this point's row
            float aph[PD];
            const float4* mp4 = (const float4*)(mu_phi + (size_t)i * PD);
            #pragma unroll
            for (int j = 0; j < 8; ++j) {
                float4 t4 = mp4[j];
                aph[4 * j + 0] = t4.x; aph[4 * j + 1] = t4.y;
                aph[4 * j + 2] = t4.z; aph[4 * j + 3] = t4.w;
            }
            float na = 0.0f;
            #pragma unroll
            for (int p = 0; p < PD; ++p) na = fmaf(aph[p], aph[p], na);

            float lcp = lcp_g[i];
            float ec  = __expf(lcp);
            float tP  = 32.0f * ec;

            // stage into shared for GEMM2
            #pragma unroll
            for (int j = 0; j < 16; ++j)
                ASMp[tid * 17 + j] = pk2(aph[2 * j], aph[2 * j + 1]);
            ECp[tid] = ec;
            NAp[tid] = na;

            // GEMM1: 64 dots via f32x2 over cluster pairs
            unsigned long long acc[32];
            #pragma unroll
            for (int k2 = 0; k2 < 32; ++k2) acc[k2] = 0ull;
            #pragma unroll
            for (int p = 0; p < PD; ++p) {
                unsigned long long ap2 = pk2(aph[p], aph[p]);
                #pragma unroll
                for (int k2 = 0; k2 < 32; ++k2)
                    acc[k2] = fma2(ap2, MUK2[p * 32 + k2], acc[k2]);
            }

            // epilogue: w_k = A_k * exp(-0.5*icov*(P*e^lcp + sq))
            float wsum = 0.0f;
            #pragma unroll
            for (int k2 = 0; k2 < 32; ++k2) {
                float d0, d1;
                upk2(acc[k2], d0, d1);
                int k0 = 2 * k2;
                float sq0 = na - 2.0f * d0 + NB[k0];
                float sq1 = na - 2.0f * d1 + NB[k0 + 1];
                float w0 = AK[k0]     * __expf(-0.5f * ICOV[k0]     * (tP + sq0));
                float w1 = AK[k0 + 1] * __expf(-0.5f * ICOV[k0 + 1] * (tP + sq1));
                wsum += w0 + w1;
                acc[k2] = pk2(w0, w1);
            }
            float rs = 1.0f / wsum;
            unsigned long long rs2 = pk2(rs, rs), dt2 = pk2(DETC, DETC);
            #pragma unroll
            for (int k2 = 0; k2 < 32; ++k2)
                acc[k2] = fma2(acc[k2], rs2, dt2);   // gamma = w*rs + DET

            // store gamma to global (16B stores, per-thread contiguous row)
            ulonglong2* grow = (ulonglong2*)(gamma_out + (size_t)i * KCL);
            #pragma unroll
            for (int j = 0; j < 16; ++j) {
                ulonglong2 v;
                v.x = acc[2 * j]; v.y = acc[2 * j + 1];
                grow[j] = v;
            }
            // store gamma transposed into shared (conflict-free: pt across banks)
            #pragma unroll
            for (int k2 = 0; k2 < 32; ++k2) {
                float g0, g1;
                upk2(acc[k2], g0, g1);
                GT[(2 * k2) * 257 + tid]     = g0;
                GT[(2 * k2 + 1) * 257 + tid] = g1;
            }
        } else {
            // invalid tail point: zero everything it contributes
            ECp[tid] = 0.0f;
            NAp[tid] = 0.0f;
            #pragma unroll
            for (int j = 0; j < 16; ++j) ASMp[tid * 17 + j] = 0ull;
            for (int k = 0; k < KCL; ++k) GT[k * 257 + tid] = 0.0f;
        }
        __syncthreads();

        // GEMM2: M_k += gamma^T @ mu_phi tile + stats, block-cooperative
        const int pb = q * 64;
        for (int u = 0; u < 64; ++u) {
            int pt = pb + u;
            float g0 = GT[gr0 + pt];
            float g1 = GT[gr1 + pt];
            unsigned long long ga = pk2(g0, g0), gb = pk2(g1, g1);
            const unsigned long long* arow = ASMp + pt * 17 + ph * 8;
            #pragma unroll
            for (int j = 0; j < 8; ++j) {
                unsigned long long a = arow[j];
                macc0[j] = fma2(ga, a, macc0[j]);
                macc1[j] = fma2(gb, a, macc1[j]);
            }
            float gk = ph ? g1 : g0;     // stats for k == r
            nacc += gk;
            eacc = fmaf(gk, ECp[pt], eacc);
            sacc = fmaf(gk, NAp[pt], sacc);
        }
    }

    // ---- block-level combine of the 4 point-quarter partials (no atomics) ----
    __syncthreads();
    unsigned long long* SB = (unsigned long long*)sm;   // 256*16 ull = 32 KB (reuse)
    float* SSn = (float*)(sm + 32768);
    float* SSe = SSn + 256;
    float* SSs = SSe + 256;
    #pragma unroll
    for (int j = 0; j < 8; ++j) {
        SB[tid * 16 + j]     = macc0[j];
        SB[tid * 16 + 8 + j] = macc1[j];
    }
    SSn[tid] = nacc; SSe[tid] = eacc; SSs[tid] = sacc;
    __syncthreads();

    const int bid = blockIdx.x;
    for (int o = tid; o < 1024; o += 256) {
        int ro = o >> 4, jo = o & 15;
        float s0 = 0.0f, s1 = 0.0f;
        #pragma unroll
        for (int qq = 0; qq < 4; ++qq) {
            float x0, x1;
            upk2(SB[((qq << 6) | ro) * 16 + jo], x0, x1);
            s0 += x0; s1 += x1;
        }
        int kk = 2 * (ro >> 1) + (jo >> 3);
        int pp = 2 * (((ro & 1) << 3) + (jo & 7));
        g_scratch[(kk * PD + pp) * NBLK + bid]     = s0;
        g_scratch[(kk * PD + pp + 1) * NBLK + bid] = s1;
    }
    if (tid < KCL) {
        float n = 0.0f, e = 0.0f, s = 0.0f;
        #pragma unroll
        for (int qq = 0; qq < 4; ++qq) {
            n += SSn[(qq << 6) | tid];
            e += SSe[(qq << 6) | tid];
            s += SSs[(qq << 6) | tid];
        }
        g_scratch[(2048 + tid) * NBLK + bid] = n;
        g_scratch[(2112 + tid) * NBLK + bid] = e;
        g_scratch[(2176 + tid) * NBLK + bid] = s;
    }
}

__global__ void deeplpm_finalize(float* __restrict__ pi_out,
                                 float* __restrict__ mu_out,
                                 float* __restrict__ lc_out,
                                 int N, int nblk) {
    __shared__ float acc[2240];
    const int t = threadIdx.x;
    for (int e = t; e < 2240; e += 256) {
        const float* p = g_scratch + (size_t)e * NBLK;
        float s = 0.0f;
        int b = 0;
        for (; b + 4 <= nblk; b += 4)
            s += p[b] + p[b + 1] + p[b + 2] + p[b + 3];
        for (; b < nblk; ++b) s += p[b];
        acc[e] = s;
    }
    __syncthreads();
    if (t < KCL) {
        float Nk = acc[2048 + t];
        float Ek = acc[2112 + t];
        float Sk = acc[2176 + t];
        pi_out[t] = Nk / (float)N;
        float inv = 1.0f / Nk;
        float nm2 = 0.0f;
        #pragma unroll
        for (int p = 0; p < PD; ++p) {
            float m = acc[t * PD + p] * inv;
            mu_out[t * PD + p] = m;
            nm2 = fmaf(m, m, nm2);
        }
        float cov = (32.0f * Ek + Sk - Nk * nm2) / (32.0f * Nk);
        lc_out[t] = logf(cov);
    }
}

extern "C" void kernel_launch(void* const* d_in, const int* in_sizes, int n_in,
                              void* d_out, int out_size) {
    const float* mu_phi = (const float*)d_in[0];
    const float* lcp    = (const float*)d_in[1];
    const float* pi_k   = (const float*)d_in[2];
    const float* mu_k   = (const float*)d_in[3];
    const float* lck    = (const float*)d_in[4];
    const int N = in_sizes[0] / PD;

    float* out     = (float*)d_out;
    float* gamma_o = out;
    float* pi_o    = out + (size_t)N * KCL;
    float* mu_o    = pi_o + KCL;
    float* lc_o    = mu_o + KCL * PD;

    int tiles = (N + TILE - 1) / TILE;
    int grid  = tiles < NBLK ? tiles : NBLK;

    cudaFuncSetAttribute(deeplpm_main,
                         cudaFuncAttributeMaxDynamicSharedMemorySize, SMEM_BYTES);

    deeplpm_main<<<grid, 256, SMEM_BYTES>>>(mu_phi, lcp, pi_k, mu_k, lck,
                                            gamma_o, N);
    deeplpm_finalize<<<1, 256>>>(pi_o, mu_o, lc_o, N, grid);
}

// round 4
// speedup vs baseline: 2.2645x; 2.2645x over previous
#include <cuda_runtime.h>

#define KCL   64
#define PD    32
#define NBLK  296
#define TILE  256
#define DETC  1e-16f
#define NENT  2240

// ---- shared memory layout (bytes) ----
#define OFF_MUK2   0          // ull[32*32]    (packed cluster pairs, [p][k2])  8192 B
#define OFF_ASM    8192       // ull[256*17]   (mu_phi tile, p-pairs, pad)     34816 B
#define OFF_GT     43008      // float[64*257] (gamma tile transposed [k][pt]) 65792 B
#define OFF_EC     108800     // float[256]    exp(lcp) per point
#define OFF_NA     109824     // float[256]    ||x||^2 per point
#define OFF_AK     110848     // float[64]     pi_k * exp(-16*lck)
#define OFF_ICOV   111104     // float[64]     exp(-lck)
#define OFF_NB     111360     // float[64]     ||mu_k||^2
#define SMEM_BYTES 111616

// per-block partial sums, layout [block][entry]:
// entry 0..2047 = M[k][p], 2048..2111 = N_k, 2112..2175 = E_k, 2176..2239 = S2_k
__device__ float g_scratch[NBLK * NENT];
__device__ float g_acc[NENT];

__device__ __forceinline__ unsigned long long pk2(float lo, float hi) {
    unsigned long long u;
    asm("mov.b64 %0, {%1,%2};" : "=l"(u) : "f"(lo), "f"(hi));
    return u;
}
__device__ __forceinline__ void upk2(unsigned long long u, float& lo, float& hi) {
    asm("mov.b64 {%0,%1}, %2;" : "=f"(lo), "=f"(hi) : "l"(u));
}
__device__ __forceinline__ unsigned long long fma2(unsigned long long a,
                                                   unsigned long long b,
                                                   unsigned long long c) {
    unsigned long long d;
    asm("fma.rn.f32x2 %0, %1, %2, %3;" : "=l"(d) : "l"(a), "l"(b), "l"(c));
    return d;
}

__global__ __launch_bounds__(256, 1)
void deeplpm_main(const float* __restrict__ mu_phi,
                  const float* __restrict__ lcp_g,
                  const float* __restrict__ pi_k,
                  const float* __restrict__ mu_k,
                  const float* __restrict__ lck_g,
                  float* __restrict__ gamma_out,
                  int N) {
    extern __shared__ unsigned char sm[];
    unsigned long long* MUK2 = (unsigned long long*)(sm + OFF_MUK2);
    unsigned long long* ASMp = (unsigned long long*)(sm + OFF_ASM);
    float* GT   = (float*)(sm + OFF_GT);
    float* ECp  = (float*)(sm + OFF_EC);
    float* NAp  = (float*)(sm + OFF_NA);
    float* AK   = (float*)(sm + OFF_AK);
    float* ICOV = (float*)(sm + OFF_ICOV);
    float* NB   = (float*)(sm + OFF_NB);

    const int tid = threadIdx.x;

    // ---- init: pack mu_k pairs + per-cluster params ----
    for (int idx = tid; idx < 1024; idx += 256) {
        int k2 = idx & 31, p = idx >> 5;
        float b0 = mu_k[(2 * k2) * PD + p];
        float b1 = mu_k[(2 * k2 + 1) * PD + p];
        MUK2[p * 32 + k2] = pk2(b0, b1);
    }
    if (tid < KCL) {
        float lck = lck_g[tid];
        ICOV[tid] = __expf(-lck);
        AK[tid]   = pi_k[tid] * __expf(-16.0f * lck);
        float nb = 0.0f;
        #pragma unroll
        for (int p = 0; p < PD; ++p) {
            float v = mu_k[tid * PD + p];
            nb = fmaf(v, v, nb);
        }
        NB[tid] = nb;
    }
    __syncthreads();

    // GEMM2 role of this thread
    const int q  = tid >> 6;       // point-quarter 0..3
    const int r  = tid & 63;
    const int kp = r >> 1;         // cluster pair 0..31
    const int ph = r & 1;          // p-half 0/1
    const int gr0 = (2 * kp) * 257;
    const int gr1 = (2 * kp + 1) * 257;

    unsigned long long macc0[8], macc1[8];
    #pragma unroll
    for (int j = 0; j < 8; ++j) { macc0[j] = 0ull; macc1[j] = 0ull; }
    float nacc = 0.0f, eacc = 0.0f, sacc = 0.0f;

    const int tiles = (N + TILE - 1) >> 8;

    for (int tile = blockIdx.x; tile < tiles; tile += gridDim.x) {
        __syncthreads();   // protect shared from previous iteration's GEMM2 readers
        const int i = tile * TILE + tid;
        if (i < N) {
            // load this point's row
            float aph[PD];
            const float4* mp4 = (const float4*)(mu_phi + (size_t)i * PD);
            #pragma unroll
            for (int j = 0; j < 8; ++j) {
                float4 t4 = mp4[j];
                aph[4 * j + 0] = t4.x; aph[4 * j + 1] = t4.y;
                aph[4 * j + 2] = t4.z; aph[4 * j + 3] = t4.w;
            }
            float na = 0.0f;
            #pragma unroll
            for (int p = 0; p < PD; ++p) na = fmaf(aph[p], aph[p], na);

            float lcp = lcp_g[i];
            float ec  = __expf(lcp);
            float tP  = 32.0f * ec;

            // stage into shared for GEMM2
            #pragma unroll
            for (int j = 0; j < 16; ++j)
                ASMp[tid * 17 + j] = pk2(aph[2 * j], aph[2 * j + 1]);
            ECp[tid] = ec;
            NAp[tid] = na;

            // GEMM1: 64 dots via f32x2 over cluster pairs
            unsigned long long acc[32];
            #pragma unroll
            for (int k2 = 0; k2 < 32; ++k2) acc[k2] = 0ull;
            #pragma unroll
            for (int p = 0; p < PD; ++p) {
                unsigned long long ap2 = pk2(aph[p], aph[p]);
                #pragma unroll
                for (int k2 = 0; k2 < 32; ++k2)
                    acc[k2] = fma2(ap2, MUK2[p * 32 + k2], acc[k2]);
            }

            // epilogue: w_k = A_k * exp(-0.5*icov*(P*e^lcp + sq))
            float wsum = 0.0f;
            #pragma unroll
            for (int k2 = 0; k2 < 32; ++k2) {
                float d0, d1;
                upk2(acc[k2], d0, d1);
                int k0 = 2 * k2;
                float sq0 = na - 2.0f * d0 + NB[k0];
                float sq1 = na - 2.0f * d1 + NB[k0 + 1];
                float w0 = AK[k0]     * __expf(-0.5f * ICOV[k0]     * (tP + sq0));
                float w1 = AK[k0 + 1] * __expf(-0.5f * ICOV[k0 + 1] * (tP + sq1));
                wsum += w0 + w1;
                acc[k2] = pk2(w0, w1);
            }
            float rs = 1.0f / wsum;
            unsigned long long rs2 = pk2(rs, rs), dt2 = pk2(DETC, DETC);
            #pragma unroll
            for (int k2 = 0; k2 < 32; ++k2)
                acc[k2] = fma2(acc[k2], rs2, dt2);   // gamma = w*rs + DET

            // store gamma to global (16B stores, per-thread contiguous row)
            ulonglong2* grow = (ulonglong2*)(gamma_out + (size_t)i * KCL);
            #pragma unroll
            for (int j = 0; j < 16; ++j) {
                ulonglong2 v;
                v.x = acc[2 * j]; v.y = acc[2 * j + 1];
                grow[j] = v;
            }
            // store gamma transposed into shared (conflict-free: pt across banks)
            #pragma unroll
            for (int k2 = 0; k2 < 32; ++k2) {
                float g0, g1;
                upk2(acc[k2], g0, g1);
                GT[(2 * k2) * 257 + tid]     = g0;
                GT[(2 * k2 + 1) * 257 + tid] = g1;
            }
        } else {
            // invalid tail point: zero everything it contributes
            ECp[tid] = 0.0f;
            NAp[tid] = 0.0f;
            #pragma unroll
            for (int j = 0; j < 16; ++j) ASMp[tid * 17 + j] = 0ull;
            for (int k = 0; k < KCL; ++k) GT[k * 257 + tid] = 0.0f;
        }
        __syncthreads();

        // GEMM2: M_k += gamma^T @ mu_phi tile + stats, block-cooperative
        const int pb = q * 64;
        for (int u = 0; u < 64; ++u) {
            int pt = pb + u;
            float g0 = GT[gr0 + pt];
            float g1 = GT[gr1 + pt];
            unsigned long long ga = pk2(g0, g0), gb = pk2(g1, g1);
            const unsigned long long* arow = ASMp + pt * 17 + ph * 8;
            #pragma unroll
            for (int j = 0; j < 8; ++j) {
                unsigned long long a = arow[j];
                macc0[j] = fma2(ga, a, macc0[j]);
                macc1[j] = fma2(gb, a, macc1[j]);
            }
            float gk = ph ? g1 : g0;     // stats for k == r
            nacc += gk;
            eacc = fmaf(gk, ECp[pt], eacc);
            sacc = fmaf(gk, NAp[pt], sacc);
        }
    }

    // ---- block-level combine of the 4 point-quarter partials (no atomics) ----
    __syncthreads();
    unsigned long long* SB = (unsigned long long*)sm;   // 256*16 ull = 32 KB (reuse)
    float* SSn = (float*)(sm + 32768);
    float* SSe = SSn + 256;
    float* SSs = SSe + 256;
    #pragma unroll
    for (int j = 0; j < 8; ++j) {
        SB[tid * 16 + j]     = macc0[j];
        SB[tid * 16 + 8 + j] = macc1[j];
    }
    SSn[tid] = nacc; SSe[tid] = eacc; SSs[tid] = sacc;
    __syncthreads();

    float* my_scratch = g_scratch + (size_t)blockIdx.x * NENT;
    for (int o = tid; o < 1024; o += 256) {
        int ro = o >> 4, jo = o & 15;
        float s0 = 0.0f, s1 = 0.0f;
        #pragma unroll
        for (int qq = 0; qq < 4; ++qq) {
            float x0, x1;
            upk2(SB[((qq << 6) | ro) * 16 + jo], x0, x1);
            s0 += x0; s1 += x1;
        }
        int kk = 2 * (ro >> 1) + (jo >> 3);
        int pp = 2 * (((ro & 1) << 3) + (jo & 7));
        my_scratch[kk * PD + pp]     = s0;
        my_scratch[kk * PD + pp + 1] = s1;
    }
    if (tid < KCL) {
        float n = 0.0f, e = 0.0f, s = 0.0f;
        #pragma unroll
        for (int qq = 0; qq < 4; ++qq) {
            n += SSn[(qq << 6) | tid];
            e += SSe[(qq << 6) | tid];
            s += SSs[(qq << 6) | tid];
        }
        my_scratch[2048 + tid] = n;
        my_scratch[2112 + tid] = e;
        my_scratch[2176 + tid] = s;
    }
}

// Stage 1: reduce g_scratch[nblk][NENT] -> g_acc[NENT].
// Coalesced: consecutive threads read consecutive entries; 4-way unrolled
// over blocks for MLP>=4 (hides DRAM latency / PTW entirely).
__global__ __launch_bounds__(256)
void deeplpm_reduce(int nblk) {
    int e = blockIdx.x * 256 + threadIdx.x;
    if (e >= NENT) return;
    const float* p = g_scratch + e;
    float s0 = 0.0f, s1 = 0.0f, s2 = 0.0f, s3 = 0.0f;
    int b = 0;
    for (; b + 4 <= nblk; b += 4) {
        s0 += p[(size_t)(b + 0) * NENT];
        s1 += p[(size_t)(b + 1) * NENT];
        s2 += p[(size_t)(b + 2) * NENT];
        s3 += p[(size_t)(b + 3) * NENT];
    }
    for (; b < nblk; ++b) s0 += p[(size_t)b * NENT];
    g_acc[e] = (s0 + s1) + (s2 + s3);
}

// Stage 2: final per-cluster math (tiny).
__global__ __launch_bounds__(64)
void deeplpm_finalize(float* __restrict__ pi_out,
                      float* __restrict__ mu_out,
                      float* __restrict__ lc_out,
                      int N) {
    int t = threadIdx.x;
    if (t >= KCL) return;
    float Nk = g_acc[2048 + t];
    float Ek = g_acc[2112 + t];
    float Sk = g_acc[2176 + t];
    pi_out[t] = Nk / (float)N;
    float inv = 1.0f / Nk;
    float nm2 = 0.0f;
    #pragma unroll
    for (int p = 0; p < PD; ++p) {
        float m = g_acc[t * PD + p] * inv;
        mu_out[t * PD + p] = m;
        nm2 = fmaf(m, m, nm2);
    }
    float cov = (32.0f * Ek + Sk - Nk * nm2) / (32.0f * Nk);
    lc_out[t] = logf(cov);
}

extern "C" void kernel_launch(void* const* d_in, const int* in_sizes, int n_in,
                              void* d_out, int out_size) {
    const float* mu_phi = (const float*)d_in[0];
    const float* lcp    = (const float*)d_in[1];
    const float* pi_k   = (const float*)d_in[2];
    const float* mu_k   = (const float*)d_in[3];
    const float* lck    = (const float*)d_in[4];
    const int N = in_sizes[0] / PD;

    float* out     = (float*)d_out;
    float* gamma_o = out;
    float* pi_o    = out + (size_t)N * KCL;
    float* mu_o    = pi_o + KCL;
    float* lc_o    = mu_o + KCL * PD;

    int tiles = (N + TILE - 1) / TILE;
    int grid  = tiles < NBLK ? tiles : NBLK;

    cudaFuncSetAttribute(deeplpm_main,
                         cudaFuncAttributeMaxDynamicSharedMemorySize, SMEM_BYTES);

    deeplpm_main<<<grid, 256, SMEM_BYTES>>>(mu_phi, lcp, pi_k, mu_k, lck,
                                            gamma_o, N);
    deeplpm_reduce<<<(NENT + 255) / 256, 256>>>(grid);
    deeplpm_finalize<<<1, 64>>>(pi_o, mu_o, lc_o, N);
}